// round 13
// baseline (speedup 1.0000x reference)
#include <cuda_runtime.h>
#include <cstdint>

#define BB 8
#define GSZ 512
#define CC 32

// RULE: g_* symbols are referenced ONLY inside device code (host-shadow bug, R1-R4).
__device__ __align__(16) unsigned g_key[BB * GSZ * GSZ];            // 8 MB
__device__ __align__(16) float g_grid[BB * GSZ * GSZ];
__device__ __align__(16) unsigned char g_m1[BB * GSZ * GSZ];
__device__ __align__(16) unsigned char g_m2[BB * 256 * 256];
__device__ __align__(16) unsigned char g_m3[BB * 128 * 128];
__device__ __align__(16) unsigned char g_m4[BB * 64 * 64];
__device__ __align__(16) float g_y1[(size_t)BB * GSZ * GSZ * CC];
__device__ __align__(16) float g_y2[(size_t)BB * 256 * 256 * CC];
__device__ __align__(16) float g_y3[(size_t)BB * 128 * 128 * CC];
__device__ __align__(16) float g_y4[(size_t)BB * 64 * 64 * CC];
// weights, coalesced layout: [L][t][qq][co][4] ; lane co reads float4 #(t*8+qq)*32+co
__device__ __align__(16) float g_wt[3 * 9 * 8 * 32 * 4];

// ---------------- scatter: LAST-write-wins, key-only 32-bit atomics --------
__global__ void k_scatter(const int* __restrict__ coords, int n) {
    int i = blockIdx.x * blockDim.x + threadIdx.x;
    if (i >= n) return;
    int b = __ldg(&coords[3 * i + 0]);
    int y = __ldg(&coords[3 * i + 1]);
    int x = __ldg(&coords[3 * i + 2]);
    atomicMax(&g_key[((size_t)b * GSZ + y) * GSZ + x], (unsigned)(i + 1));
}

// ---------------- decode: key -> mask + gathered feat; self-clearing -------
__global__ void k_decode(const float* __restrict__ feats) {
    int n = BB * GSZ * GSZ;
    for (int i = blockIdx.x * blockDim.x + threadIdx.x; i < n; i += gridDim.x * blockDim.x) {
        unsigned v = g_key[i];
        g_m1[i] = v ? (unsigned char)1 : (unsigned char)0;
        g_grid[i] = v ? __ldg(&feats[v - 1]) : 0.0f;
        if (v) g_key[i] = 0;                     // conditional clear (sparse writes)
    }
}

// ---------------- conv1 (16x32 tiles) + fused aux (maskall / wtrans) -------
__global__ void k_conv1(const float* __restrict__ K1, const float* __restrict__ K2,
                        const float* __restrict__ K3, const float* __restrict__ K4) {
    if (blockIdx.z == BB) {
        int bid = blockIdx.y * 32 + blockIdx.x;
        if (bid < 128) {
            int i = bid * 256 + threadIdx.x;
            int X = i & 63;
            int Y = (i >> 6) & 63;
            int b = i >> 12;
            const unsigned char* m1b = g_m1 + ((size_t)b * GSZ + 8 * Y) * GSZ + 8 * X;
            unsigned m2row[4];
            unsigned allor = 0;
#pragma unroll
            for (int r2 = 0; r2 < 4; r2++) {
                uint2 a = *(const uint2*)(m1b + (2 * r2) * GSZ);
                uint2 c = *(const uint2*)(m1b + (2 * r2 + 1) * GSZ);
                unsigned u = a.x | c.x;
                unsigned v = a.y | c.y;
                unsigned tu = u | (u >> 8);
                unsigned tv = v | (v >> 8);
                unsigned res = (tu & 0xFFu) | (((tu >> 16) & 0xFFu) << 8) |
                               ((tv & 0xFFu) << 16) | (((tv >> 16) & 0xFFu) << 24);
                m2row[r2] = res;
                allor |= res;
                *(unsigned*)(g_m2 + ((size_t)b * 256 + 4 * Y + r2) * 256 + 4 * X) = res;
            }
#pragma unroll
            for (int r3 = 0; r3 < 2; r3++) {
                unsigned w = m2row[2 * r3] | m2row[2 * r3 + 1];
                unsigned s = w | (w >> 8);
                unsigned short m3v = (unsigned short)((s & 0xFFu) | (((s >> 16) & 0xFFu) << 8));
                *(unsigned short*)(g_m3 + ((size_t)b * 128 + 2 * Y + r3) * 128 + 2 * X) = m3v;
            }
            unsigned o = allor;
            o |= o >> 16;
            o |= o >> 8;
            g_m4[((size_t)b * 64 + Y) * 64 + X] = (unsigned char)(o & 1u);
        } else if (bid < 131) {
            int L = bid - 128;
            const float* src = (L == 0) ? K2 : (L == 1) ? K3 : K4;
            float* dst = g_wt + L * 9216;
            // dst[((t*8+qq)*32+co)*4 + j] = src[(t*32 + qq*4 + j)*32 + co]
            for (int i = threadIdx.x; i < 9216; i += 256) {
                int t = i >> 10;
                int rem = i & 1023;
                int ci = rem >> 5;          // 0..31
                int co = rem & 31;
                int qq = ci >> 2;
                int j = ci & 3;
                dst[((t * 8 + qq) * 32 + co) * 4 + j] = __ldg(&src[i]);
            }
        }
        return;
    }

    __shared__ float in_s[36 * 20];
    __shared__ unsigned omask[32];

    int tid = threadIdx.x;
    int b = blockIdx.z;
    int ox0 = blockIdx.x * 16;
    int oy0 = blockIdx.y * 32;
    int co = tid & 31;
    int wid = tid >> 5;

    float w[25];
#pragma unroll
    for (int t = 0; t < 25; t++) w[t] = __ldg(&K1[t * 32 + co]);

    for (int p = tid; p < 720; p += 256) {
        int r = p / 20;
        int c = p - r * 20;
        int gy = oy0 + r - 2;
        int gx = ox0 + c - 2;
        float v = 0.0f;
        if ((unsigned)gy < (unsigned)GSZ && (unsigned)gx < (unsigned)GSZ)
            v = g_grid[((size_t)b * GSZ + gy) * GSZ + gx];
        in_s[p] = v;
    }
    if (tid < 32) {
        uint4 m = __ldg((const uint4*)(g_m1 + ((size_t)b * GSZ + oy0 + tid) * GSZ + ox0));
        unsigned wv[4] = {m.x, m.y, m.z, m.w};
        unsigned bits = 0;
#pragma unroll
        for (int j = 0; j < 4; j++)
#pragma unroll
            for (int k = 0; k < 4; k++)
                if ((wv[j] >> (8 * k)) & 0xFFu) bits |= 1u << (j * 4 + k);
        omask[tid] = bits;
    }
    __syncthreads();

#pragma unroll
    for (int rr = 0; rr < 4; rr++) {
        int py = wid + rr * 8;
        unsigned bm = omask[py];
        float* orow = g_y1 + (((size_t)b * GSZ + oy0 + py) * GSZ + ox0) * 32 + co;
        while (bm) {
            int px = __ffs(bm) - 1;
            bm &= bm - 1;
            float acc = 0.0f;
#pragma unroll
            for (int t = 0; t < 25; t++) {
                int dy = t / 5;
                int dx = t - dy * 5;
                acc = fmaf(in_s[(py + dy) * 20 + px + dx], w[t], acc);
            }
            orow[px * 32] = fmaxf(acc, 0.0f);
        }
    }
}

// ---------------- SPARSE 3x3 stride-2 pad-1 conv, 32->32 ch ----------------
// R10 geometry: tile 8x8, 37KB smem, 4 blocks/SM. NEW: tap loop fully
// unrolled -> all weight/input/mask addresses become immediates.
#define C2_INS (289 * 32)                    // 17*17 cells x 32 ch floats
#define C2_SMEM (C2_INS * 4 + 17 * 20 + 2 + 289 * 2 + 51 + 128)

template <int L>
__global__ __launch_bounds__(256, 4) void k_conv_s2() {
    const float* in = (L == 0) ? g_y1 : (L == 1) ? g_y2 : g_y3;
    float* out = (L == 0) ? g_y2 : (L == 1) ? g_y3 : g_y4;
    const unsigned char* mi = (L == 0) ? g_m1 : (L == 1) ? g_m2 : g_m3;
    const unsigned char* mo = (L == 0) ? g_m2 : (L == 1) ? g_m3 : g_m4;
    const int Hin = (L == 0) ? 512 : (L == 1) ? 256 : 128;
    const int Hout = Hin / 2;

    extern __shared__ float smem[];
    float* in_s = smem;                                        // [289][32]
    unsigned char* m_s = (unsigned char*)(smem + C2_INS);      // [17][20]
    unsigned short* s_cell = (unsigned short*)(m_s + 17 * 20 + 2);  // [289]
    unsigned char* em = (unsigned char*)(s_cell + 289);        // [17][3] tap masks
    __shared__ int s_nact;

    int tid = threadIdx.x;
    int lane = tid & 31;
    int b = blockIdx.z;
    int ox0 = blockIdx.x * 8;
    int oy0 = blockIdx.y * 8;
    int ix0 = 2 * ox0 - 1;
    int iy0 = 2 * oy0 - 1;

    const float* in_b = in + (size_t)b * Hin * Hin * 32;
    const unsigned char* mi_b = mi + (size_t)b * Hin * Hin;

    if (tid == 0) s_nact = 0;
    __syncthreads();

    // Phase A: mask scan (289 cells) + warp-aggregated compaction
#pragma unroll
    for (int it = 0; it < 2; it++) {
        int p = tid + it * 256;
        bool valid = p < 289;
        unsigned char mv = 0;
        if (valid) {
            int r = p / 17;
            int c = p - r * 17;
            int gy = iy0 + r;
            int gx = ix0 + c;
            if ((unsigned)gy < (unsigned)Hin && (unsigned)gx < (unsigned)Hin)
                mv = mi_b[gy * Hin + gx];
            m_s[r * 20 + c] = mv;
        }
        unsigned vote = __ballot_sync(0xFFFFFFFFu, valid && mv);
        int base = 0;
        if (lane == 0 && vote) base = atomicAdd(&s_nact, __popc(vote));
        base = __shfl_sync(0xFFFFFFFFu, base, 0);
        if (valid && mv) {
            int pos = base + __popc(vote & ((1u << lane) - 1));
            s_cell[pos] = (unsigned short)p;
        }
    }
    __syncthreads();

    // Phase A2: per-(row,dx) tap masks: bit px = m_s[row][2*px+dx]
    if (tid < 51) {
        int r = tid / 3;
        int dx = tid - r * 3;
        unsigned bits = 0;
#pragma unroll
        for (int px = 0; px < 8; px++)
            if (m_s[r * 20 + 2 * px + dx]) bits |= 1u << px;
        em[r * 3 + dx] = (unsigned char)bits;
    }

    // Phase B: flat copy of active cells only (MLP-friendly)
    int nact = s_nact;
    for (int i = tid; i < nact * 8; i += 256) {
        int k = i >> 3;
        int q = i & 7;
        int cell = s_cell[k];
        int r = cell / 17;
        int c = cell - r * 17;
        int gy = iy0 + r;
        int gx = ix0 + c;
        float4 v = __ldg((const float4*)(in_b + (size_t)(gy * Hin + gx) * 32) + q);
        ((float4*)(in_s + cell * 32))[q] = v;
    }
    __syncthreads();

    int py = tid >> 5;
    int co = tid & 31;
    int oy = oy0 + py;
    unsigned sm = __ballot_sync(0xFFFFFFFFu,
        (co < 8) && mo[((size_t)b * Hout + oy) * Hout + ox0 + (co & 7)]);

    if (sm) {
        float acc[8];
#pragma unroll
        for (int i = 0; i < 8; i++) acc[i] = 0.0f;
        // hoisted bases: all subsequent offsets are compile-time immediates
        const float4* wco = (const float4*)(g_wt + L * 9216) + co;     // + (t*8+qq)*32
        const float* wrow = in_s + (2 * py) * 17 * 32;                 // + (dy*17+dx)*32 + px*64 + ...
        const unsigned char* emw = em + (2 * py) * 3;                  // + dy*3 + dx

#pragma unroll
        for (int t = 0; t < 9; t++) {
            const int dy = t / 3;
            const int dx = t - dy * 3;
            unsigned bm = (unsigned)emw[dy * 3 + dx] & sm;   // immediate-offset LDS
            if (!bm) continue;
            float4 wq[8];
#pragma unroll
            for (int qq = 0; qq < 8; qq++)
                wq[qq] = __ldg(wco + (t * 8 + qq) * 32);     // immediate offsets
            const float* irow = wrow + (dy * 17 + dx) * 32;
#pragma unroll
            for (int px = 0; px < 8; px++) {
                if (bm & (1u << px)) {                // warp-uniform branch
                    const float4* ip = (const float4*)(irow + px * 64);
#pragma unroll
                    for (int qq = 0; qq < 8; qq++) {
                        float4 a = ip[qq];
                        acc[px] = fmaf(a.x, wq[qq].x, acc[px]);
                        acc[px] = fmaf(a.y, wq[qq].y, acc[px]);
                        acc[px] = fmaf(a.z, wq[qq].z, acc[px]);
                        acc[px] = fmaf(a.w, wq[qq].w, acc[px]);
                    }
                }
            }
        }
        float* orow = out + (((size_t)b * Hout + oy) * Hout + ox0) * 32 + co;
#pragma unroll
        for (int px = 0; px < 8; px++) {
            if (sm & (1u << px)) orow[px * 32] = fmaxf(acc[px], 0.0f);
        }
    }
}

// ---------------- masked global pool + MLP head (1024 threads) -------------
__global__ void k_final(
    const float* __restrict__ x2,
    const float* __restrict__ W1, const float* __restrict__ b1,
    const float* __restrict__ W2, const float* __restrict__ b2,
    const float* __restrict__ W3, const float* __restrict__ b3,
    float* __restrict__ out)
{
    __shared__ float s_pool[32][32];
    __shared__ int s_cnt[32];
    __shared__ float s_z[64];
    __shared__ float s_t1[64];

    int b = blockIdx.x;
    int tid = threadIdx.x;
    int wg = tid >> 5;
    int lane = tid & 31;

    float ps = 0.0f;
    int pc = 0;
    const float* y4b = g_y4 + (size_t)b * 4096 * 32;
    const unsigned char* m4b = g_m4 + (size_t)b * 4096;
    for (int p = wg; p < 4096; p += 32) {
        if (m4b[p]) {
            ps += y4b[(size_t)p * 32 + lane];
            pc++;
        }
    }
    s_pool[wg][lane] = ps;
    if (lane == 0) s_cnt[wg] = pc;
    __syncthreads();

    if (tid < 32) {
        float s = 0.0f;
        int c = 0;
#pragma unroll
        for (int w = 0; w < 32; w++) { s += s_pool[w][tid]; c += s_cnt[w]; }
        s_z[tid] = s / fmaxf((float)c, 1.0f);
    }
    if (tid >= 32 && tid < 96) {
        int t = tid - 32;
        float a = b1[t];
        a = fmaf(x2[b * 3 + 0], W1[0 * 64 + t], a);
        a = fmaf(x2[b * 3 + 1], W1[1 * 64 + t], a);
        a = fmaf(x2[b * 3 + 2], W1[2 * 64 + t], a);
        s_t1[t] = fmaxf(a, 0.0f);
    }
    __syncthreads();
    if (tid < 32) {
        float a = b2[tid];
#pragma unroll
        for (int k = 0; k < 64; k++) a = fmaf(s_t1[k], W2[k * 32 + tid], a);
        s_z[32 + tid] = a;
    }
    __syncthreads();
    if (tid < 128) {
        float a = b3[tid];
#pragma unroll
        for (int k = 0; k < 64; k++) a = fmaf(s_z[k], W3[k * 128 + tid], a);
        out[b * 128 + tid] = fmaxf(a, 0.0f);
    }
}

// ---------------- launch: #4 = k_conv_s2<0> (profiled slot) ----------------
extern "C" void kernel_launch(void* const* d_in, const int* in_sizes, int n_in,
                              void* d_out, int out_size) {
    const int* coords = (const int*)d_in[0];
    const float* feats = (const float*)d_in[1];
    const float* x2 = (const float*)d_in[2];
    const float* K1 = (const float*)d_in[3];
    const float* K2 = (const float*)d_in[4];
    const float* K3 = (const float*)d_in[5];
    const float* K4 = (const float*)d_in[6];
    const float* W1 = (const float*)d_in[7];
    const float* b1 = (const float*)d_in[8];
    const float* W2 = (const float*)d_in[9];
    const float* b2 = (const float*)d_in[10];
    const float* W3 = (const float*)d_in[11];
    const float* b3 = (const float*)d_in[12];
    float* out = (float*)d_out;

    int npts = in_sizes[0] / 3;  // 262144

    cudaFuncSetAttribute(k_conv_s2<0>, cudaFuncAttributeMaxDynamicSharedMemorySize, C2_SMEM);
    cudaFuncSetAttribute(k_conv_s2<1>, cudaFuncAttributeMaxDynamicSharedMemorySize, C2_SMEM);
    cudaFuncSetAttribute(k_conv_s2<2>, cudaFuncAttributeMaxDynamicSharedMemorySize, C2_SMEM);

    k_scatter<<<(npts + 255) / 256, 256>>>(coords, npts);
    k_decode<<<4096, 256>>>(feats);
    k_conv1<<<dim3(32, 16, BB + 1), 256>>>(K1, K2, K3, K4);
    k_conv_s2<0><<<dim3(32, 32, BB), 256, C2_SMEM>>>();
    k_conv_s2<1><<<dim3(16, 16, BB), 256, C2_SMEM>>>();
    k_conv_s2<2><<<dim3(8, 8, BB), 256, C2_SMEM>>>();
    k_final<<<BB, 1024>>>(x2, W1, b1, W2, b2, W3, b3, out);
}

// round 14
// speedup vs baseline: 1.3143x; 1.3143x over previous
#include <cuda_runtime.h>
#include <cstdint>

#define BB 8
#define GSZ 512
#define CC 32

// RULE: g_* symbols are referenced ONLY inside device code (host-shadow bug, R1-R4).
__device__ __align__(16) unsigned g_key[BB * GSZ * GSZ];            // 8 MB
__device__ __align__(16) float g_grid[BB * GSZ * GSZ];
__device__ __align__(16) unsigned char g_m1[BB * GSZ * GSZ];
__device__ __align__(16) unsigned char g_m2[BB * 256 * 256];
__device__ __align__(16) unsigned char g_m3[BB * 128 * 128];
__device__ __align__(16) unsigned char g_m4[BB * 64 * 64];
__device__ __align__(16) float g_y1[(size_t)BB * GSZ * GSZ * CC];
__device__ __align__(16) float g_y2[(size_t)BB * 256 * 256 * CC];
__device__ __align__(16) float g_y3[(size_t)BB * 128 * 128 * CC];
__device__ __align__(16) float g_y4[(size_t)BB * 64 * 64 * CC];
// weights, coalesced layout: [L][t][qq][co][4] ; lane co reads float4 #(t*8+qq)*32+co
__device__ __align__(16) float g_wt[3 * 9 * 8 * 32 * 4];

// ---------------- scatter: LAST-write-wins, key-only 32-bit atomics --------
__global__ void k_scatter(const int* __restrict__ coords, int n) {
    int i = blockIdx.x * blockDim.x + threadIdx.x;
    if (i >= n) return;
    int b = __ldg(&coords[3 * i + 0]);
    int y = __ldg(&coords[3 * i + 1]);
    int x = __ldg(&coords[3 * i + 2]);
    atomicMax(&g_key[((size_t)b * GSZ + y) * GSZ + x], (unsigned)(i + 1));
}

// ---------------- decode: key -> mask + gathered feat; self-clearing -------
__global__ void k_decode(const float* __restrict__ feats) {
    int n = BB * GSZ * GSZ;
    for (int i = blockIdx.x * blockDim.x + threadIdx.x; i < n; i += gridDim.x * blockDim.x) {
        unsigned v = g_key[i];
        g_m1[i] = v ? (unsigned char)1 : (unsigned char)0;
        g_grid[i] = v ? __ldg(&feats[v - 1]) : 0.0f;
        if (v) g_key[i] = 0;                     // conditional clear (sparse writes)
    }
}

// ---------------- conv1 (16x32 tiles) + fused aux (maskall / wtrans) -------
__global__ void k_conv1(const float* __restrict__ K1, const float* __restrict__ K2,
                        const float* __restrict__ K3, const float* __restrict__ K4) {
    if (blockIdx.z == BB) {
        int bid = blockIdx.y * 32 + blockIdx.x;
        if (bid < 128) {
            int i = bid * 256 + threadIdx.x;
            int X = i & 63;
            int Y = (i >> 6) & 63;
            int b = i >> 12;
            const unsigned char* m1b = g_m1 + ((size_t)b * GSZ + 8 * Y) * GSZ + 8 * X;
            unsigned m2row[4];
            unsigned allor = 0;
#pragma unroll
            for (int r2 = 0; r2 < 4; r2++) {
                uint2 a = *(const uint2*)(m1b + (2 * r2) * GSZ);
                uint2 c = *(const uint2*)(m1b + (2 * r2 + 1) * GSZ);
                unsigned u = a.x | c.x;
                unsigned v = a.y | c.y;
                unsigned tu = u | (u >> 8);
                unsigned tv = v | (v >> 8);
                unsigned res = (tu & 0xFFu) | (((tu >> 16) & 0xFFu) << 8) |
                               ((tv & 0xFFu) << 16) | (((tv >> 16) & 0xFFu) << 24);
                m2row[r2] = res;
                allor |= res;
                *(unsigned*)(g_m2 + ((size_t)b * 256 + 4 * Y + r2) * 256 + 4 * X) = res;
            }
#pragma unroll
            for (int r3 = 0; r3 < 2; r3++) {
                unsigned w = m2row[2 * r3] | m2row[2 * r3 + 1];
                unsigned s = w | (w >> 8);
                unsigned short m3v = (unsigned short)((s & 0xFFu) | (((s >> 16) & 0xFFu) << 8));
                *(unsigned short*)(g_m3 + ((size_t)b * 128 + 2 * Y + r3) * 128 + 2 * X) = m3v;
            }
            unsigned o = allor;
            o |= o >> 16;
            o |= o >> 8;
            g_m4[((size_t)b * 64 + Y) * 64 + X] = (unsigned char)(o & 1u);
        } else if (bid < 131) {
            int L = bid - 128;
            const float* src = (L == 0) ? K2 : (L == 1) ? K3 : K4;
            float* dst = g_wt + L * 9216;
            // dst[((t*8+qq)*32+co)*4 + j] = src[(t*32 + qq*4 + j)*32 + co]
            for (int i = threadIdx.x; i < 9216; i += 256) {
                int t = i >> 10;
                int rem = i & 1023;
                int ci = rem >> 5;          // 0..31
                int co = rem & 31;
                int qq = ci >> 2;
                int j = ci & 3;
                dst[((t * 8 + qq) * 32 + co) * 4 + j] = __ldg(&src[i]);
            }
        }
        return;
    }

    __shared__ float in_s[36 * 20];
    __shared__ unsigned omask[32];

    int tid = threadIdx.x;
    int b = blockIdx.z;
    int ox0 = blockIdx.x * 16;
    int oy0 = blockIdx.y * 32;
    int co = tid & 31;
    int wid = tid >> 5;

    float w[25];
#pragma unroll
    for (int t = 0; t < 25; t++) w[t] = __ldg(&K1[t * 32 + co]);

    for (int p = tid; p < 720; p += 256) {
        int r = p / 20;
        int c = p - r * 20;
        int gy = oy0 + r - 2;
        int gx = ox0 + c - 2;
        float v = 0.0f;
        if ((unsigned)gy < (unsigned)GSZ && (unsigned)gx < (unsigned)GSZ)
            v = g_grid[((size_t)b * GSZ + gy) * GSZ + gx];
        in_s[p] = v;
    }
    if (tid < 32) {
        uint4 m = __ldg((const uint4*)(g_m1 + ((size_t)b * GSZ + oy0 + tid) * GSZ + ox0));
        unsigned wv[4] = {m.x, m.y, m.z, m.w};
        unsigned bits = 0;
#pragma unroll
        for (int j = 0; j < 4; j++)
#pragma unroll
            for (int k = 0; k < 4; k++)
                if ((wv[j] >> (8 * k)) & 0xFFu) bits |= 1u << (j * 4 + k);
        omask[tid] = bits;
    }
    __syncthreads();

#pragma unroll
    for (int rr = 0; rr < 4; rr++) {
        int py = wid + rr * 8;
        unsigned bm = omask[py];
        float* orow = g_y1 + (((size_t)b * GSZ + oy0 + py) * GSZ + ox0) * 32 + co;
        while (bm) {
            int px = __ffs(bm) - 1;
            bm &= bm - 1;
            float acc = 0.0f;
#pragma unroll
            for (int t = 0; t < 25; t++) {
                int dy = t / 5;
                int dx = t - dy * 5;
                acc = fmaf(in_s[(py + dy) * 20 + px + dx], w[t], acc);
            }
            orow[px * 32] = fmaxf(acc, 0.0f);
        }
    }
}

// ---------------- SPARSE 3x3 stride-2 pad-1 conv, 32->32 ch ----------------
// R10/R11 structure (dynamic tap loop). Change: 5 blocks/SM, weight fetch in
// two 4-float4 halves to fit the 48-reg budget without spilling.
#define C2_INS (289 * 32)                    // 17*17 cells x 32 ch floats
#define C2_SMEM (C2_INS * 4 + 17 * 20 + 2 + 289 * 2 + 51 + 128)

template <int L>
__global__ __launch_bounds__(256, 5) void k_conv_s2() {
    const float* in = (L == 0) ? g_y1 : (L == 1) ? g_y2 : g_y3;
    float* out = (L == 0) ? g_y2 : (L == 1) ? g_y3 : g_y4;
    const unsigned char* mi = (L == 0) ? g_m1 : (L == 1) ? g_m2 : g_m3;
    const unsigned char* mo = (L == 0) ? g_m2 : (L == 1) ? g_m3 : g_m4;
    const int Hin = (L == 0) ? 512 : (L == 1) ? 256 : 128;
    const int Hout = Hin / 2;

    extern __shared__ float smem[];
    float* in_s = smem;                                        // [289][32]
    unsigned char* m_s = (unsigned char*)(smem + C2_INS);      // [17][20]
    unsigned short* s_cell = (unsigned short*)(m_s + 17 * 20 + 2);  // [289]
    unsigned char* em = (unsigned char*)(s_cell + 289);        // [17][3] tap masks
    __shared__ int s_nact;

    int tid = threadIdx.x;
    int lane = tid & 31;
    int b = blockIdx.z;
    int ox0 = blockIdx.x * 8;
    int oy0 = blockIdx.y * 8;
    int ix0 = 2 * ox0 - 1;
    int iy0 = 2 * oy0 - 1;

    const float* in_b = in + (size_t)b * Hin * Hin * 32;
    const unsigned char* mi_b = mi + (size_t)b * Hin * Hin;

    if (tid == 0) s_nact = 0;
    __syncthreads();

    // Phase A: mask scan (289 cells) + warp-aggregated compaction
#pragma unroll
    for (int it = 0; it < 2; it++) {
        int p = tid + it * 256;
        bool valid = p < 289;
        unsigned char mv = 0;
        if (valid) {
            int r = p / 17;
            int c = p - r * 17;
            int gy = iy0 + r;
            int gx = ix0 + c;
            if ((unsigned)gy < (unsigned)Hin && (unsigned)gx < (unsigned)Hin)
                mv = mi_b[gy * Hin + gx];
            m_s[r * 20 + c] = mv;
        }
        unsigned vote = __ballot_sync(0xFFFFFFFFu, valid && mv);
        int base = 0;
        if (lane == 0 && vote) base = atomicAdd(&s_nact, __popc(vote));
        base = __shfl_sync(0xFFFFFFFFu, base, 0);
        if (valid && mv) {
            int pos = base + __popc(vote & ((1u << lane) - 1));
            s_cell[pos] = (unsigned short)p;
        }
    }
    __syncthreads();

    // Phase A2: per-(row,dx) tap masks: bit px = m_s[row][2*px+dx]
    if (tid < 51) {
        int r = tid / 3;
        int dx = tid - r * 3;
        unsigned bits = 0;
#pragma unroll
        for (int px = 0; px < 8; px++)
            if (m_s[r * 20 + 2 * px + dx]) bits |= 1u << px;
        em[r * 3 + dx] = (unsigned char)bits;
    }

    // Phase B: flat copy of active cells only (MLP-friendly)
    int nact = s_nact;
    for (int i = tid; i < nact * 8; i += 256) {
        int k = i >> 3;
        int q = i & 7;
        int cell = s_cell[k];
        int r = cell / 17;
        int c = cell - r * 17;
        int gy = iy0 + r;
        int gx = ix0 + c;
        float4 v = __ldg((const float4*)(in_b + (size_t)(gy * Hin + gx) * 32) + q);
        ((float4*)(in_s + cell * 32))[q] = v;
    }
    __syncthreads();

    int py = tid >> 5;
    int co = tid & 31;
    int oy = oy0 + py;
    unsigned sm = __ballot_sync(0xFFFFFFFFu,
        (co < 8) && mo[((size_t)b * Hout + oy) * Hout + ox0 + (co & 7)]);

    if (sm) {
        float acc[8];
#pragma unroll
        for (int i = 0; i < 8; i++) acc[i] = 0.0f;
        const float4* wbase4 = (const float4*)(g_wt + L * 9216);

#pragma unroll 1
        for (int t = 0; t < 9; t++) {
            int dy = t / 3;
            int dx = t - dy * 3;
            int row = 2 * py + dy;
            unsigned bm = (unsigned)em[row * 3 + dx] & sm;   // broadcast LDS + AND
            if (!bm) continue;
            const float* irow = in_s + (row * 17 + dx) * 32;
            // half 0: qq 0..3
            {
                float4 wq[4];
#pragma unroll
                for (int qq = 0; qq < 4; qq++)
                    wq[qq] = __ldg(wbase4 + (t * 8 + qq) * 32 + co);
#pragma unroll
                for (int px = 0; px < 8; px++) {
                    if (bm & (1u << px)) {                // warp-uniform branch
                        const float4* ip = (const float4*)(irow + px * 64);
#pragma unroll
                        for (int qq = 0; qq < 4; qq++) {
                            float4 a = ip[qq];
                            acc[px] = fmaf(a.x, wq[qq].x, acc[px]);
                            acc[px] = fmaf(a.y, wq[qq].y, acc[px]);
                            acc[px] = fmaf(a.z, wq[qq].z, acc[px]);
                            acc[px] = fmaf(a.w, wq[qq].w, acc[px]);
                        }
                    }
                }
            }
            // half 1: qq 4..7
            {
                float4 wq[4];
#pragma unroll
                for (int qq = 0; qq < 4; qq++)
                    wq[qq] = __ldg(wbase4 + (t * 8 + 4 + qq) * 32 + co);
#pragma unroll
                for (int px = 0; px < 8; px++) {
                    if (bm & (1u << px)) {
                        const float4* ip = (const float4*)(irow + px * 64) + 4;
#pragma unroll
                        for (int qq = 0; qq < 4; qq++) {
                            float4 a = ip[qq];
                            acc[px] = fmaf(a.x, wq[qq].x, acc[px]);
                            acc[px] = fmaf(a.y, wq[qq].y, acc[px]);
                            acc[px] = fmaf(a.z, wq[qq].z, acc[px]);
                            acc[px] = fmaf(a.w, wq[qq].w, acc[px]);
                        }
                    }
                }
            }
        }
        float* orow = out + (((size_t)b * Hout + oy) * Hout + ox0) * 32 + co;
#pragma unroll
        for (int px = 0; px < 8; px++) {
            if (sm & (1u << px)) orow[px * 32] = fmaxf(acc[px], 0.0f);
        }
    }
}

// ---------------- masked global pool + MLP head (1024 threads) -------------
__global__ void k_final(
    const float* __restrict__ x2,
    const float* __restrict__ W1, const float* __restrict__ b1,
    const float* __restrict__ W2, const float* __restrict__ b2,
    const float* __restrict__ W3, const float* __restrict__ b3,
    float* __restrict__ out)
{
    __shared__ float s_pool[32][32];
    __shared__ int s_cnt[32];
    __shared__ float s_z[64];
    __shared__ float s_t1[64];

    int b = blockIdx.x;
    int tid = threadIdx.x;
    int wg = tid >> 5;
    int lane = tid & 31;

    float ps = 0.0f;
    int pc = 0;
    const float* y4b = g_y4 + (size_t)b * 4096 * 32;
    const unsigned char* m4b = g_m4 + (size_t)b * 4096;
    for (int p = wg; p < 4096; p += 32) {
        if (m4b[p]) {
            ps += y4b[(size_t)p * 32 + lane];
            pc++;
        }
    }
    s_pool[wg][lane] = ps;
    if (lane == 0) s_cnt[wg] = pc;
    __syncthreads();

    if (tid < 32) {
        float s = 0.0f;
        int c = 0;
#pragma unroll
        for (int w = 0; w < 32; w++) { s += s_pool[w][tid]; c += s_cnt[w]; }
        s_z[tid] = s / fmaxf((float)c, 1.0f);
    }
    if (tid >= 32 && tid < 96) {
        int t = tid - 32;
        float a = b1[t];
        a = fmaf(x2[b * 3 + 0], W1[0 * 64 + t], a);
        a = fmaf(x2[b * 3 + 1], W1[1 * 64 + t], a);
        a = fmaf(x2[b * 3 + 2], W1[2 * 64 + t], a);
        s_t1[t] = fmaxf(a, 0.0f);
    }
    __syncthreads();
    if (tid < 32) {
        float a = b2[tid];
#pragma unroll
        for (int k = 0; k < 64; k++) a = fmaf(s_t1[k], W2[k * 32 + tid], a);
        s_z[32 + tid] = a;
    }
    __syncthreads();
    if (tid < 128) {
        float a = b3[tid];
#pragma unroll
        for (int k = 0; k < 64; k++) a = fmaf(s_z[k], W3[k * 128 + tid], a);
        out[b * 128 + tid] = fmaxf(a, 0.0f);
    }
}

// ---------------- launch: #4 = k_conv_s2<0> (profiled slot) ----------------
extern "C" void kernel_launch(void* const* d_in, const int* in_sizes, int n_in,
                              void* d_out, int out_size) {
    const int* coords = (const int*)d_in[0];
    const float* feats = (const float*)d_in[1];
    const float* x2 = (const float*)d_in[2];
    const float* K1 = (const float*)d_in[3];
    const float* K2 = (const float*)d_in[4];
    const float* K3 = (const float*)d_in[5];
    const float* K4 = (const float*)d_in[6];
    const float* W1 = (const float*)d_in[7];
    const float* b1 = (const float*)d_in[8];
    const float* W2 = (const float*)d_in[9];
    const float* b2 = (const float*)d_in[10];
    const float* W3 = (const float*)d_in[11];
    const float* b3 = (const float*)d_in[12];
    float* out = (float*)d_out;

    int npts = in_sizes[0] / 3;  // 262144

    cudaFuncSetAttribute(k_conv_s2<0>, cudaFuncAttributeMaxDynamicSharedMemorySize, C2_SMEM);
    cudaFuncSetAttribute(k_conv_s2<1>, cudaFuncAttributeMaxDynamicSharedMemorySize, C2_SMEM);
    cudaFuncSetAttribute(k_conv_s2<2>, cudaFuncAttributeMaxDynamicSharedMemorySize, C2_SMEM);

    k_scatter<<<(npts + 255) / 256, 256>>>(coords, npts);
    k_decode<<<4096, 256>>>(feats);
    k_conv1<<<dim3(32, 16, BB + 1), 256>>>(K1, K2, K3, K4);
    k_conv_s2<0><<<dim3(32, 32, BB), 256, C2_SMEM>>>();
    k_conv_s2<1><<<dim3(16, 16, BB), 256, C2_SMEM>>>();
    k_conv_s2<2><<<dim3(8, 8, BB), 256, C2_SMEM>>>();
    k_final<<<BB, 1024>>>(x2, W1, b1, W2, b2, W3, b3, out);
}